// round 3
// baseline (speedup 1.0000x reference)
#include <cuda_runtime.h>
#include <math.h>

// Problem constants (fixed shapes for this benchmark)
#define B_Q   4096
#define P_POS 4
#define D_DIM 768
#define N_ROWS (B_Q + B_Q * P_POS)   // 20480 rows in combined matrix [q; d]
#define NJT   (N_ROWS / 128)         // 160 column tiles
#define NIT   (B_Q / 128)            // 32 row tiles

// GEMM tile config
#define BM 128
#define BN 128
#define BK 16
#define TM 8
#define TN 8
#define NKT (D_DIM / BK)             // 48

// log2(e) / 0.07
#define SCALE 20.60992915555662f

// Scratch (static device globals; no runtime allocation)
__device__ float g_M[(size_t)N_ROWS * D_DIM];      // normalized [q; d]  (~63 MB)
__device__ float g_part[(size_t)NJT * B_Q];        // per (jtile, i) partial sums
__device__ float g_A[B_Q * P_POS];                 // positive-pair exp values
__device__ float g_qloss[B_Q];                     // per-query loss

__device__ __forceinline__ float ex2(float x) {
    float r;
    asm("ex2.approx.f32 %0, %1;" : "=f"(r) : "f"(x));
    return r;
}

// ---------------------------------------------------------------------------
// Kernel 1: L2-normalize each row of q and d into g_M. One block per row.
// ---------------------------------------------------------------------------
__global__ void normalize_kernel(const float* __restrict__ q,
                                 const float* __restrict__ d) {
    const int row = blockIdx.x;
    const float* src = (row < B_Q)
        ? (q + (size_t)row * D_DIM)
        : (d + (size_t)(row - B_Q) * D_DIM);

    const int t = threadIdx.x;             // 256 threads, 3 elems each
    float v0 = src[t];
    float v1 = src[t + 256];
    float v2 = src[t + 512];
    float ss = v0 * v0 + v1 * v1 + v2 * v2;

    #pragma unroll
    for (int o = 16; o > 0; o >>= 1) ss += __shfl_xor_sync(0xffffffffu, ss, o);

    __shared__ float ws[8];
    const int lane = t & 31, wid = t >> 5;
    if (lane == 0) ws[wid] = ss;
    __syncthreads();
    if (t == 0) {
        float tot = 0.f;
        #pragma unroll
        for (int i = 0; i < 8; ++i) tot += ws[i];
        ws[0] = 1.0f / fmaxf(sqrtf(tot), 1e-12f);
    }
    __syncthreads();
    const float inv = ws[0];

    float* dst = g_M + (size_t)row * D_DIM;
    dst[t]       = v0 * inv;
    dst[t + 256] = v1 * inv;
    dst[t + 512] = v2 * inv;
}

// ---------------------------------------------------------------------------
// Kernel 2: fused GEMM + exp2 + row-sum, double-buffered SMEM.
//   C[i][j] = dot(g_M[i], g_M[j]) for i in query tile, j in any tile.
//   e = exp2(C * SCALE); row-sum e into g_part[jt][i]; positives into g_A.
// ---------------------------------------------------------------------------
#define APAD 4

__global__ __launch_bounds__(256)
void simexp_kernel() {
    const int it = blockIdx.y;
    const int jt = blockIdx.x;
    const int i0 = it * BM;
    const int j0 = jt * BN;

    __shared__ float As[2][BK][BM + APAD];
    __shared__ float Bs[2][BK][BN + APAD];
    __shared__ float red[BM][17];

    const int tid = threadIdx.x;
    const int tr = tid >> 4;        // 0..15
    const int tc = tid & 15;        // 0..15

    const int lr = tid >> 2;        // 0..63  (row within tile half)
    const int lc = (tid & 3) << 2;  // 0,4,8,12 (k offset, float4)

    const float* Ag = g_M + (size_t)(i0 + lr) * D_DIM + lc;
    const float* Bg = g_M + (size_t)(j0 + lr) * D_DIM + lc;

    float acc[TM][TN];
    #pragma unroll
    for (int m = 0; m < TM; ++m)
        #pragma unroll
        for (int n = 0; n < TN; ++n) acc[m][n] = 0.f;

    // load first K-tile into registers
    float4 a0 = *(const float4*)(Ag);
    float4 a1 = *(const float4*)(Ag + (size_t)64 * D_DIM);
    float4 b0 = *(const float4*)(Bg);
    float4 b1 = *(const float4*)(Bg + (size_t)64 * D_DIM);

    // stage buffer 0
    As[0][lc + 0][lr] = a0.x; As[0][lc + 1][lr] = a0.y;
    As[0][lc + 2][lr] = a0.z; As[0][lc + 3][lr] = a0.w;
    As[0][lc + 0][lr + 64] = a1.x; As[0][lc + 1][lr + 64] = a1.y;
    As[0][lc + 2][lr + 64] = a1.z; As[0][lc + 3][lr + 64] = a1.w;
    Bs[0][lc + 0][lr] = b0.x; Bs[0][lc + 1][lr] = b0.y;
    Bs[0][lc + 2][lr] = b0.z; Bs[0][lc + 3][lr] = b0.w;
    Bs[0][lc + 0][lr + 64] = b1.x; Bs[0][lc + 1][lr + 64] = b1.y;
    Bs[0][lc + 2][lr + 64] = b1.z; Bs[0][lc + 3][lr + 64] = b1.w;
    __syncthreads();

    int buf = 0;
    for (int kt = 0; kt < NKT; ++kt) {
        // prefetch next K-tile into registers (overlaps with math below)
        if (kt + 1 < NKT) {
            const int off = (kt + 1) * BK;
            a0 = *(const float4*)(Ag + off);
            a1 = *(const float4*)(Ag + (size_t)64 * D_DIM + off);
            b0 = *(const float4*)(Bg + off);
            b1 = *(const float4*)(Bg + (size_t)64 * D_DIM + off);
        }

        #pragma unroll
        for (int kk = 0; kk < BK; ++kk) {
            float ra[TM], rb[TN];
            *(float4*)&ra[0] = *(const float4*)&As[buf][kk][tr * TM];
            *(float4*)&ra[4] = *(const float4*)&As[buf][kk][tr * TM + 4];
            *(float4*)&rb[0] = *(const float4*)&Bs[buf][kk][tc * TN];
            *(float4*)&rb[4] = *(const float4*)&Bs[buf][kk][tc * TN + 4];
            #pragma unroll
            for (int m = 0; m < TM; ++m)
                #pragma unroll
                for (int n = 0; n < TN; ++n)
                    acc[m][n] = fmaf(ra[m], rb[n], acc[m][n]);
        }

        // stage next tile into the other buffer; single barrier per iter
        if (kt + 1 < NKT) {
            const int nb = buf ^ 1;
            As[nb][lc + 0][lr] = a0.x; As[nb][lc + 1][lr] = a0.y;
            As[nb][lc + 2][lr] = a0.z; As[nb][lc + 3][lr] = a0.w;
            As[nb][lc + 0][lr + 64] = a1.x; As[nb][lc + 1][lr + 64] = a1.y;
            As[nb][lc + 2][lr + 64] = a1.z; As[nb][lc + 3][lr + 64] = a1.w;
            Bs[nb][lc + 0][lr] = b0.x; Bs[nb][lc + 1][lr] = b0.y;
            Bs[nb][lc + 2][lr] = b0.z; Bs[nb][lc + 3][lr] = b0.w;
            Bs[nb][lc + 0][lr + 64] = b1.x; Bs[nb][lc + 1][lr + 64] = b1.y;
            Bs[nb][lc + 2][lr + 64] = b1.z; Bs[nb][lc + 3][lr + 64] = b1.w;
            __syncthreads();
            buf = nb;
        }
    }

    // ---- epilogue: exp2, positive capture, row reduce ----
    float rsum[TM];
    #pragma unroll
    for (int m = 0; m < TM; ++m) {
        rsum[m] = 0.f;
        const int gi = i0 + tr * TM + m;
        #pragma unroll
        for (int n = 0; n < TN; ++n) {
            const float v = ex2(acc[m][n] * SCALE);
            rsum[m] += v;
            const int gj = j0 + tc * TN + n;
            const unsigned rr = (unsigned)(gj - B_Q - 4 * gi);
            if (rr < 4u) g_A[gi * P_POS + (int)rr] = v;   // exactly one writer
        }
    }

    __syncthreads();   // red[] reuse barrier (after last compute)
    #pragma unroll
    for (int m = 0; m < TM; ++m) red[tr * TM + m][tc] = rsum[m];
    __syncthreads();
    if (tid < BM) {
        float s = 0.f;
        #pragma unroll
        for (int c = 0; c < 16; ++c) s += red[tid][c];
        g_part[(size_t)jt * B_Q + i0 + tid] = s;   // deterministic, no atomics
    }
}

// ---------------------------------------------------------------------------
// Kernel 3: per-query loss.
// ---------------------------------------------------------------------------
__global__ void finalize_q_kernel() {
    const int i = blockIdx.x * blockDim.x + threadIdx.x;
    if (i >= B_Q) return;

    const float* __restrict__ part = g_part;
    float S = 0.f;
    #pragma unroll 8
    for (int jt = 0; jt < NJT; ++jt) S += part[(size_t)jt * B_Q + i];

    float a[P_POS], U = 0.f;
    #pragma unroll
    for (int n = 0; n < P_POS; ++n) { a[n] = g_A[i * P_POS + n]; U += a[n]; }

    const float EXP1T = expf(1.0f / 0.07f);   // exp(1/t)
    const float base = S - EXP1T - U;

    float l = 0.f;
    #pragma unroll
    for (int n = 0; n < P_POS; ++n)
        l += logf(base + a[n]) - logf(a[n]);

    g_qloss[i] = l;
}

// ---------------------------------------------------------------------------
// Kernel 4: scalar reduce -> out.
// ---------------------------------------------------------------------------
__global__ void finalize_sum_kernel(float* __restrict__ out) {
    __shared__ float sh[256];
    const int t = threadIdx.x;
    float acc = 0.f;
    for (int i = t; i < B_Q; i += 256) acc += g_qloss[i];
    sh[t] = acc;
    __syncthreads();
    for (int s = 128; s > 0; s >>= 1) {
        if (t < s) sh[t] += sh[t + s];
        __syncthreads();
    }
    if (t == 0) out[0] = sh[0] * (1.0f / (float)(B_Q * P_POS));
}

// ---------------------------------------------------------------------------
extern "C" void kernel_launch(void* const* d_in, const int* in_sizes, int n_in,
                              void* d_out, int out_size) {
    (void)in_sizes; (void)n_in; (void)out_size;
    const float* q = (const float*)d_in[0];
    const float* d = (const float*)d_in[1];

    normalize_kernel<<<N_ROWS, 256>>>(q, d);

    dim3 grid(NJT, NIT);
    simexp_kernel<<<grid, 256>>>();

    finalize_q_kernel<<<B_Q / 256, 256>>>();
    finalize_sum_kernel<<<1, 256>>>((float*)d_out);
}

// round 6
// speedup vs baseline: 5.4820x; 5.4820x over previous
#include <cuda_runtime.h>
#include <cuda_bf16.h>
#include <math.h>
#include <stdint.h>

// Problem constants (fixed shapes)
#define B_Q   4096
#define P_POS 4
#define D_DIM 768
#define N_ROWS 20480                 // [q; d] rows
#define NJT   160                    // 20480/128 column tiles
#define NIT   32                     // 4096/128 row tiles

// log2(e)/0.07
#define SCALE 20.60992915555662f

// GEMM config: block tile 128x128, 8 warps of 64x32, BK=32 bf16
#define BK 32
#define NKT (D_DIM / BK)             // 24
#define ROWB 80                      // smem bytes per 32-half row (64B + 16B pad -> conflict-free ldmatrix)
#define STAGE_BYTES (256 * ROWB)     // A(128 rows) + B(128 rows)
#define SM_B_OFF (128 * ROWB)

// Scratch
__device__ __nv_bfloat16 g_Mh[(size_t)N_ROWS * D_DIM];  // normalized [q; d], bf16 (~31.5 MB)
__device__ float g_part[(size_t)NJT * B_Q];
__device__ float g_A[B_Q * P_POS];
__device__ float g_diag[B_Q];        // computed exp(q_i.q_i/t) — cancels bf16 diag error
__device__ float g_qloss[B_Q];

__device__ __forceinline__ float ex2(float x) {
    float r;
    asm("ex2.approx.f32 %0, %1;" : "=f"(r) : "f"(x));
    return r;
}

__device__ __forceinline__ void cp16(uint32_t saddr, const void* gaddr) {
    asm volatile("cp.async.cg.shared.global [%0], [%1], 16;"
                 :: "r"(saddr), "l"(gaddr));
}

__device__ __forceinline__ void ldsm4(uint32_t* r, uint32_t addr) {
    asm volatile("ldmatrix.sync.aligned.m8n8.x4.shared.b16 {%0,%1,%2,%3}, [%4];"
                 : "=r"(r[0]), "=r"(r[1]), "=r"(r[2]), "=r"(r[3]) : "r"(addr));
}

__device__ __forceinline__ void mma16816(float* c, const uint32_t* a,
                                         uint32_t b0, uint32_t b1) {
    asm volatile(
        "mma.sync.aligned.m16n8k16.row.col.f32.bf16.bf16.f32 "
        "{%0,%1,%2,%3}, {%4,%5,%6,%7}, {%8,%9}, {%0,%1,%2,%3};"
        : "+f"(c[0]), "+f"(c[1]), "+f"(c[2]), "+f"(c[3])
        : "r"(a[0]), "r"(a[1]), "r"(a[2]), "r"(a[3]), "r"(b0), "r"(b1));
}

// ---------------------------------------------------------------------------
// Kernel 1: L2-normalize rows (fp32 math) -> bf16 g_Mh. One block per row.
// ---------------------------------------------------------------------------
__global__ void normalize_kernel(const float* __restrict__ q,
                                 const float* __restrict__ d) {
    const int row = blockIdx.x;
    const float* src = (row < B_Q)
        ? (q + (size_t)row * D_DIM)
        : (d + (size_t)(row - B_Q) * D_DIM);

    const int t = threadIdx.x;             // 256 threads, 3 elems each
    float v0 = src[t];
    float v1 = src[t + 256];
    float v2 = src[t + 512];
    float ss = v0 * v0 + v1 * v1 + v2 * v2;

    #pragma unroll
    for (int o = 16; o > 0; o >>= 1) ss += __shfl_xor_sync(0xffffffffu, ss, o);

    __shared__ float ws[8];
    const int lane = t & 31, wid = t >> 5;
    if (lane == 0) ws[wid] = ss;
    __syncthreads();
    if (t == 0) {
        float tot = 0.f;
        #pragma unroll
        for (int i = 0; i < 8; ++i) tot += ws[i];
        ws[0] = 1.0f / fmaxf(sqrtf(tot), 1e-12f);
    }
    __syncthreads();
    const float inv = ws[0];

    __nv_bfloat16* dst = g_Mh + (size_t)row * D_DIM;
    dst[t]       = __float2bfloat16_rn(v0 * inv);
    dst[t + 256] = __float2bfloat16_rn(v1 * inv);
    dst[t + 512] = __float2bfloat16_rn(v2 * inv);
}

// ---------------------------------------------------------------------------
// Kernel 2: bf16 tensor-core GEMM + exp2 + row-sum.
//   Block tile 128(i) x 128(j); 8 warps (2 m x 4 n), warp tile 64x32.
//   2-stage cp.async pipeline over K.
// ---------------------------------------------------------------------------
__global__ __launch_bounds__(256, 2)
void simexp_kernel() {
    __shared__ __align__(128) unsigned char smbuf[2][STAGE_BYTES];
    __shared__ float red[128][5];

    const int tid  = threadIdx.x;
    const int lane = tid & 31;
    const int w    = tid >> 5;
    const int wm   = w >> 2;          // 0..1  (m position, 64 rows each)
    const int wn   = w & 3;           // 0..3  (n position, 32 cols each)

    const int it = blockIdx.y, jt = blockIdx.x;
    const int i0 = it * 128, j0 = jt * 128;

    const uint32_t smbase = (uint32_t)__cvta_generic_to_shared(&smbuf[0][0]);

    // loader mapping: 256 threads x 2 iters cover 128 rows x 4 chunks(16B)
    const int lr  = tid >> 2;         // 0..63  (rows lr, lr+64)
    const int lcq = tid & 3;          // 16B chunk 0..3

    const __nv_bfloat16* Ag   = g_Mh + (size_t)(i0 + lr) * D_DIM + lcq * 8;
    const __nv_bfloat16* Ag64 = Ag + (size_t)64 * D_DIM;
    const __nv_bfloat16* Bg   = g_Mh + (size_t)(j0 + lr) * D_DIM + lcq * 8;
    const __nv_bfloat16* Bg64 = Bg + (size_t)64 * D_DIM;

    const uint32_t sA_row = (uint32_t)lr * ROWB + lcq * 16;
    const uint32_t sA_row64 = sA_row + 64 * ROWB;

    // ldmatrix base offsets (per lane)
    const uint32_t lm_a = (uint32_t)(wm * 64 + (lane & 15)) * ROWB + (lane >> 4) * 16;
    const uint32_t lm_b0 = (uint32_t)(wn * 32 + (lane & 15)) * ROWB + (lane >> 4) * 16;
    const uint32_t lm_b1 = lm_b0 + 16 * ROWB;

    float acc[4][4][4];
    #pragma unroll
    for (int mt = 0; mt < 4; ++mt)
        #pragma unroll
        for (int nt = 0; nt < 4; ++nt)
            #pragma unroll
            for (int i = 0; i < 4; ++i) acc[mt][nt][i] = 0.f;

    // prologue: stage 0
    {
        const uint32_t sa = smbase;
        cp16(sa + sA_row, Ag);
        cp16(sa + sA_row64, Ag64);
        cp16(sa + SM_B_OFF + sA_row, Bg);
        cp16(sa + SM_B_OFF + sA_row64, Bg64);
        asm volatile("cp.async.commit_group;" ::: "memory");
    }

    for (int kt = 0; kt < NKT; ++kt) {
        if (kt + 1 < NKT) {
            const uint32_t sa = smbase + ((kt + 1) & 1) * STAGE_BYTES;
            const int off = (kt + 1) * BK;
            cp16(sa + sA_row, Ag + off);
            cp16(sa + sA_row64, Ag64 + off);
            cp16(sa + SM_B_OFF + sA_row, Bg + off);
            cp16(sa + SM_B_OFF + sA_row64, Bg64 + off);
            asm volatile("cp.async.commit_group;" ::: "memory");
            asm volatile("cp.async.wait_group 1;" ::: "memory");
        } else {
            asm volatile("cp.async.wait_group 0;" ::: "memory");
        }
        __syncthreads();

        const uint32_t sA = smbase + (kt & 1) * STAGE_BYTES;
        const uint32_t sB = sA + SM_B_OFF;

        #pragma unroll
        for (int kk = 0; kk < 2; ++kk) {          // two k16 steps (byte offset kk*32)
            uint32_t a[4][4];
            #pragma unroll
            for (int mt = 0; mt < 4; ++mt)
                ldsm4(a[mt], sA + lm_a + mt * 16 * ROWB + kk * 32);

            uint32_t b[2][4];
            ldsm4(b[0], sB + lm_b0 + kk * 32);
            ldsm4(b[1], sB + lm_b1 + kk * 32);

            #pragma unroll
            for (int mt = 0; mt < 4; ++mt)
                #pragma unroll
                for (int nt = 0; nt < 4; ++nt) {
                    const int p = nt >> 1, h = nt & 1;
                    mma16816(acc[mt][nt], a[mt], b[p][h], b[p][h + 2]);
                }
        }
        __syncthreads();
    }

    // ---- epilogue: exp2, positive/diag capture, row reduce ----
    const int rbase = wm * 64 + (lane >> 2);      // + mt*16 (+8 for hi half)
    const int cbase = j0 + wn * 32 + 2 * (lane & 3);

    // docs for queries [i0, i0+128) live at rows B_Q+4*i0 .. B_Q+4*(i0+128)
    const bool may_capture = (j0 + 128 > B_Q + 4 * i0) && (j0 < B_Q + 4 * (i0 + 128));
    // q-q diagonal lives only in tiles with j0 == i0
    const bool may_diag = (j0 == i0);

    #pragma unroll
    for (int mt = 0; mt < 4; ++mt) {
        float rs_lo = 0.f, rs_hi = 0.f;
        const int gi_lo = i0 + rbase + mt * 16;
        const int gi_hi = gi_lo + 8;
        #pragma unroll
        for (int nt = 0; nt < 4; ++nt) {
            const int gj = cbase + nt * 8;
            const float e0 = ex2(acc[mt][nt][0] * SCALE);
            const float e1 = ex2(acc[mt][nt][1] * SCALE);
            const float e2 = ex2(acc[mt][nt][2] * SCALE);
            const float e3 = ex2(acc[mt][nt][3] * SCALE);
            rs_lo += e0 + e1;
            rs_hi += e2 + e3;
            if (may_capture) {
                // positive capture: docs for query gi live at rows B_Q + 4*gi .. +3
                unsigned rr;
                rr = (unsigned)(gj     - B_Q - 4 * gi_lo); if (rr < 4u) g_A[gi_lo * P_POS + (int)rr] = e0;
                rr = (unsigned)(gj + 1 - B_Q - 4 * gi_lo); if (rr < 4u) g_A[gi_lo * P_POS + (int)rr] = e1;
                rr = (unsigned)(gj     - B_Q - 4 * gi_hi); if (rr < 4u) g_A[gi_hi * P_POS + (int)rr] = e2;
                rr = (unsigned)(gj + 1 - B_Q - 4 * gi_hi); if (rr < 4u) g_A[gi_hi * P_POS + (int)rr] = e3;
            }
            if (may_diag) {
                // capture computed diagonal exp(q_i.q_i/t): cancels bf16 norm error
                if (gj     == gi_lo) g_diag[gi_lo] = e0;
                if (gj + 1 == gi_lo) g_diag[gi_lo] = e1;
                if (gj     == gi_hi) g_diag[gi_hi] = e2;
                if (gj + 1 == gi_hi) g_diag[gi_hi] = e3;
            }
        }
        // reduce across the 4 lanes of the quad (same rows)
        rs_lo += __shfl_xor_sync(0xffffffffu, rs_lo, 1);
        rs_lo += __shfl_xor_sync(0xffffffffu, rs_lo, 2);
        rs_hi += __shfl_xor_sync(0xffffffffu, rs_hi, 1);
        rs_hi += __shfl_xor_sync(0xffffffffu, rs_hi, 2);
        if ((lane & 3) == 0) {
            red[rbase + mt * 16][wn]     = rs_lo;
            red[rbase + mt * 16 + 8][wn] = rs_hi;
        }
    }
    __syncthreads();

    if (tid < 128) {
        const float s = red[tid][0] + red[tid][1] + red[tid][2] + red[tid][3];
        g_part[(size_t)jt * B_Q + i0 + tid] = s;   // deterministic, no atomics
    }
}

// ---------------------------------------------------------------------------
// Kernel 3: per-query loss. Subtract COMPUTED diagonal (exact cancellation).
// ---------------------------------------------------------------------------
__global__ void finalize_q_kernel() {
    const int i = blockIdx.x * blockDim.x + threadIdx.x;
    if (i >= B_Q) return;

    const float* __restrict__ part = g_part;
    float S = 0.f;
    #pragma unroll 8
    for (int jt = 0; jt < NJT; ++jt) S += part[(size_t)jt * B_Q + i];

    float a[P_POS], U = 0.f;
    #pragma unroll
    for (int n = 0; n < P_POS; ++n) { a[n] = g_A[i * P_POS + n]; U += a[n]; }

    // In exact math diag == exp(1/t); using the computed value cancels the
    // bf16 self-dot error that otherwise amplifies 40x in the denominator.
    const float base = S - g_diag[i] - U;

    float l = 0.f;
    #pragma unroll
    for (int n = 0; n < P_POS; ++n)
        l += logf(base + a[n]) - logf(a[n]);

    g_qloss[i] = l;
}

// ---------------------------------------------------------------------------
// Kernel 4: scalar reduce -> out.
// ---------------------------------------------------------------------------
__global__ void finalize_sum_kernel(float* __restrict__ out) {
    __shared__ float sh[256];
    const int t = threadIdx.x;
    float acc = 0.f;
    for (int i = t; i < B_Q; i += 256) acc += g_qloss[i];
    sh[t] = acc;
    __syncthreads();
    for (int s = 128; s > 0; s >>= 1) {
        if (t < s) sh[t] += sh[t + s];
        __syncthreads();
    }
    if (t == 0) out[0] = sh[0] * (1.0f / (float)(B_Q * P_POS));
}

// ---------------------------------------------------------------------------
extern "C" void kernel_launch(void* const* d_in, const int* in_sizes, int n_in,
                              void* d_out, int out_size) {
    (void)in_sizes; (void)n_in; (void)out_size;
    const float* q = (const float*)d_in[0];
    const float* d = (const float*)d_in[1];

    normalize_kernel<<<N_ROWS, 256>>>(q, d);

    dim3 grid(NJT, NIT);
    simexp_kernel<<<grid, 256>>>();

    finalize_q_kernel<<<B_Q / 256, 256>>>();
    finalize_sum_kernel<<<1, 256>>>((float*)d_out);
}